// round 10
// baseline (speedup 1.0000x reference)
#include <cuda_runtime.h>
#include <cstdint>

// Problem constants
#define M_SUB   8
#define N_E     1024
#define E_DIM   64
#define BS_     16
#define CC_     512
#define HW_     1024
#define NPOS    16384            // BS_*HW_

// Output layout (float32)
#define OFF_ZVQ  0
#define OFF_LOSS 8388608
#define OFF_IDX  8388609
#define OFF_BIN  8519681

#define CAP   32        // candidate cap per row
#define EPSF  2e-3f     // collect threshold (>= 3x worst-case tf32 error bound)

// Scratch (device globals; no allocation allowed)
__device__ float  g_esq[M_SUB * N_E];
// packed codebooks for mma fragments: [m][ch(16)][kp(32)][j(64)] float2
//   kp = ks*4 + lxr  ->  k0 = 8*ks + lxr ; float2 = (cb[k0][c], cb[k0+4][c]), c = ch*64 + j
__device__ float2 g_cbt2[M_SUB * 16 * 2048];
__device__ double g_part[1024];

// ---------------- helpers ------------------------------------------------------
__device__ __forceinline__ void mma_tf32(float& d0, float& d1, float& d2, float& d3,
                                         unsigned a0, unsigned a1, unsigned a2, unsigned a3,
                                         unsigned b0, unsigned b1) {
    asm volatile("mma.sync.aligned.m16n8k8.row.col.f32.tf32.tf32.f32 "
                 "{%0,%1,%2,%3}, {%4,%5,%6,%7}, {%8,%9}, {%0,%1,%2,%3};"
                 : "+f"(d0), "+f"(d1), "+f"(d2), "+f"(d3)
                 : "r"(a0), "r"(a1), "r"(a2), "r"(a3), "r"(b0), "r"(b1));
}

// ---------------- K0: zero bins -------------------------------------------------
__global__ void pq_init_kernel(float* __restrict__ outBins) {
    int t = threadIdx.x;
    if (t < N_E) outBins[t] = 0.0f;
}

// ---------------- K_esq: per-code squared norms (mul then sequential add) -------
__global__ void pq_esq_kernel(const float* __restrict__ cbk) {
    int t = blockIdx.x * blockDim.x + threadIdx.x;
    if (t >= M_SUB * N_E) return;
    const float* p = cbk + (size_t)t * E_DIM;
    float s = 0.0f;
    #pragma unroll
    for (int d = 0; d < E_DIM; d++) {
        float v = p[d];
        s = __fadd_rn(s, __fmul_rn(v, v));
    }
    g_esq[t] = s;
}

// ---------------- K_tr: pack codebooks into mma-fragment order ------------------
// grid = 64 blocks (8 m x 8 tiles of 128 codes = 2 chunks), 256 threads
__global__ void pq_tr_kernel(const float* __restrict__ cbk) {
    __shared__ float st[64 * 128];            // [k][code_local]
    int m  = blockIdx.x >> 3;
    int ct = (blockIdx.x & 7) * 128;
    int tid = threadIdx.x;
    int code = tid >> 1;
    int kh = (tid & 1) * 32;
    const float* src = cbk + ((size_t)(m * N_E) + ct + code) * E_DIM + kh;
    #pragma unroll
    for (int q = 0; q < 8; q++) {
        float4 v = *(const float4*)(src + q * 4);
        st[(kh + q * 4 + 0) * 128 + code] = v.x;
        st[(kh + q * 4 + 1) * 128 + code] = v.y;
        st[(kh + q * 4 + 2) * 128 + code] = v.z;
        st[(kh + q * 4 + 3) * 128 + code] = v.w;
    }
    __syncthreads();
    #pragma unroll
    for (int chl = 0; chl < 2; chl++) {
        int ch = (blockIdx.x & 7) * 2 + chl;
        float2* dst = g_cbt2 + ((size_t)m * 16 + ch) * 2048;
        #pragma unroll
        for (int it = 0; it < 8; it++) {
            int i = tid + it * 256;           // 0..2047
            int kp = i >> 6, j = i & 63;
            int k0 = ((kp >> 2) << 3) + (kp & 3);
            dst[i] = make_float2(st[k0 * 128 + chl * 64 + j],
                                 st[(k0 + 4) * 128 + chl * 64 + j]);
        }
    }
}

// ---------------- K1: tf32 MMA scoring + exact rescore + fused epilogue ---------
// Block 256 threads (8 warps). Tile: 128 rows x 1024 codes. grid = (128, 8).
// smem carve (floats):
#define S_ZT    0            // z tile [128][73]            (9344)
#define S_SPB   9344         // B dbl-buf 2 x [32][132]     (8448)
#define S_CAND  17792        // candidates [128][CAP] int   (4096)
#define S_ESQ   21888        // esq                         (1024)
#define S_ZSQ   22912        // zsq                         (128)
#define S_CNT   23040        // counters int                (128)
#define S_WIN   23168        // winners int                 (128)
#define S_RBD   23296        // rescore partial d           (256)
#define S_RBI   23552        // rescore partial idx int     (256)
#define S_TOT   23808        // 95232 bytes
#define S_SQ    9344         // gather overlay (8320 <= 8448)

__global__ void __launch_bounds__(256, 2)
pq_dist_kernel(const float* __restrict__ z,
               const float* __restrict__ cbk,
               float* __restrict__ outZvq,
               float* __restrict__ outIdx,
               float* __restrict__ outBins)
{
    extern __shared__ float sm[];
    float*    szt  = sm + S_ZT;
    float*    spb  = sm + S_SPB;
    int*      scand= (int*)(sm + S_CAND);
    float*    sesq = sm + S_ESQ;
    float*    szsq = sm + S_ZSQ;
    int*      scnt = (int*)(sm + S_CNT);
    int*      swin = (int*)(sm + S_WIN);
    float*    rbd  = sm + S_RBD;
    int*      rbi  = (int*)(sm + S_RBI);
    __shared__ double swarp[8];

    const int m  = blockIdx.y;
    const int n0 = blockIdx.x * 128;
    const int b  = n0 >> 10;
    const int p0 = n0 & 1023;
    const int tid  = threadIdx.x;
    const int wid  = tid >> 5;
    const int lane = tid & 31;
    const int gg   = lane >> 2;      // group id 0..7
    const int lx   = lane & 3;       // thread-in-group
    const int row0 = wid * 16 + gg;  // rows owned by this thread's D frags
    const float INFF = __int_as_float(0x7f800000);

    // ---- load z tile [pos][d] (transpose from gmem [d][pos]) ----
    const float* zbase = z + ((size_t)(b * CC_ + m * E_DIM) * HW_) + p0;
    #pragma unroll
    for (int it = 0; it < 8; it++) {
        int i = tid + it * 256;
        int d = i >> 5, j4 = (i & 31) * 4;
        float4 v = *(const float4*)(zbase + (size_t)d * HW_ + j4);
        szt[(j4 + 0) * 73 + d] = v.x;
        szt[(j4 + 1) * 73 + d] = v.y;
        szt[(j4 + 2) * 73 + d] = v.z;
        szt[(j4 + 3) * 73 + d] = v.w;
    }
    #pragma unroll
    for (int it = 0; it < 4; it++)
        sesq[tid + it * 256] = g_esq[m * N_E + tid + it * 256];
    if (tid < 128) scnt[tid] = 0;

    // ---- prologue: fill B buffer 0 with chunk 0 ----
    const float4* gsrc = (const float4*)(g_cbt2 + (size_t)m * 16 * 2048);
    #pragma unroll
    for (int it = 0; it < 4; it++) {
        int i4 = tid + it * 256;               // 0..1023 float4 slots
        int kp = i4 >> 5, jj = i4 & 31;
        *(float4*)(spb + kp * 132 + jj * 4) = gsrc[i4];
    }
    __syncthreads();

    // ---- per-row ||z||^2 (sequential chain, matches reference) ----
    if (tid < 128) {
        float s = 0.0f;
        const float* zr = szt + tid * 73;
        #pragma unroll
        for (int k = 0; k < E_DIM; k++)
            s = __fadd_rn(s, __fmul_rn(zr[k], zr[k]));
        szsq[tid] = s;
    }

    // ---- A fragments (held in regs): rows row0/row0+8, k=64 ----
    unsigned afr[8][4];
    {
        const float* za = szt + row0 * 73 + lx;
        const float* zb = szt + (row0 + 8) * 73 + lx;
        #pragma unroll
        for (int ks = 0; ks < 8; ks++) {
            afr[ks][0] = __float_as_uint(za[8 * ks]);
            afr[ks][1] = __float_as_uint(zb[8 * ks]);
            afr[ks][2] = __float_as_uint(za[8 * ks + 4]);
            afr[ks][3] = __float_as_uint(zb[8 * ks + 4]);
        }
    }

    // ---- 16 chunks of 64 codes: prefetch / MMA / register running-min ----
    float rmin0 = INFF, rmin1 = INFF;
    for (int ch = 0; ch < 16; ch++) {
        const float* cur = spb + (ch & 1) * 4224;
        float*       nxt = spb + ((ch + 1) & 1) * 4224;

        float4 pf[4];
        if (ch < 15) {
            const float4* s = gsrc + (ch + 1) * 1024;
            #pragma unroll
            for (int it = 0; it < 4; it++) pf[it] = s[tid + it * 256];
        }

        float acc[8][4];
        #pragma unroll
        for (int nt = 0; nt < 8; nt++)
            #pragma unroll
            for (int q = 0; q < 4; q++) acc[nt][q] = 0.0f;

        const float* bp = cur + lx * 132 + gg * 16;
        #pragma unroll
        for (int ks = 0; ks < 8; ks++) {
            const float4* b4 = (const float4*)(bp + ks * 528);
            #pragma unroll
            for (int q = 0; q < 4; q++) {
                float4 bb = b4[q];
                mma_tf32(acc[2*q][0],   acc[2*q][1],   acc[2*q][2],   acc[2*q][3],
                         afr[ks][0], afr[ks][1], afr[ks][2], afr[ks][3],
                         __float_as_uint(bb.x), __float_as_uint(bb.y));
                mma_tf32(acc[2*q+1][0], acc[2*q+1][1], acc[2*q+1][2], acc[2*q+1][3],
                         afr[ks][0], afr[ks][1], afr[ks][2], afr[ks][3],
                         __float_as_uint(bb.z), __float_as_uint(bb.w));
            }
        }

        if (ch < 15) {
            #pragma unroll
            for (int it = 0; it < 4; it++) {
                int i4 = tid + it * 256;
                int kp = i4 >> 5, jj = i4 & 31;
                *(float4*)(nxt + kp * 132 + jj * 4) = pf[it];
            }
        }

        // scores: esq[c] - 2*dot ; code for d0/d2 = ch*64+16*lx+nt, d1/d3 = +8
        float m0 = INFF, m1 = INFF;
        #pragma unroll
        for (int nt = 0; nt < 8; nt++) {
            int c0 = ch * 64 + 16 * lx + nt;
            float e0 = sesq[c0], e1 = sesq[c0 + 8];
            float s0 = __fmaf_rn(acc[nt][0], -2.0f, e0);
            float s1 = __fmaf_rn(acc[nt][1], -2.0f, e1);
            float s2 = __fmaf_rn(acc[nt][2], -2.0f, e0);
            float s3 = __fmaf_rn(acc[nt][3], -2.0f, e1);
            m0 = fminf(m0, fminf(s0, s1));
            m1 = fminf(m1, fminf(s2, s3));
        }
        #pragma unroll
        for (int off = 1; off <= 2; off <<= 1) {
            m0 = fminf(m0, __shfl_xor_sync(0xffffffffu, m0, off));
            m1 = fminf(m1, __shfl_xor_sync(0xffffffffu, m1, off));
        }
        rmin0 = fminf(rmin0, m0);
        rmin1 = fminf(rmin1, m1);
        float thr0 = rmin0 + EPSF;
        float thr1 = rmin1 + EPSF;

        #pragma unroll
        for (int nt = 0; nt < 8; nt++) {
            int c0 = ch * 64 + 16 * lx + nt;
            float e0 = sesq[c0], e1 = sesq[c0 + 8];
            float s0 = __fmaf_rn(acc[nt][0], -2.0f, e0);
            float s1 = __fmaf_rn(acc[nt][1], -2.0f, e1);
            float s2 = __fmaf_rn(acc[nt][2], -2.0f, e0);
            float s3 = __fmaf_rn(acc[nt][3], -2.0f, e1);
            if (s0 <= thr0) { int p = atomicAdd(scnt + row0, 1);     if (p < CAP) scand[row0 * CAP + p] = c0; }
            if (s1 <= thr0) { int p = atomicAdd(scnt + row0, 1);     if (p < CAP) scand[row0 * CAP + p] = c0 + 8; }
            if (s2 <= thr1) { int p = atomicAdd(scnt + row0 + 8, 1); if (p < CAP) scand[(row0 + 8) * CAP + p] = c0; }
            if (s3 <= thr1) { int p = atomicAdd(scnt + row0 + 8, 1); if (p < CAP) scand[(row0 + 8) * CAP + p] = c0 + 8; }
        }
        __syncthreads();   // all reads of `cur` done; `nxt` visible next iter
    }

    // ---- exact rescore (reference-identical fp32 chains); 2 threads per row ----
    {
        int row = (tid < 128) ? tid : tid - 128;
        int start = (tid < 128) ? 0 : 1;
        int cnt = scnt[row];
        const float* zr = szt + row * 73;
        float zsqv = szsq[row];
        const float* cbm = cbk + (size_t)m * N_E * E_DIM;
        float bd = INFF; int bi = 0x7fffffff;

        auto exact_d = [&](int c) -> float {
            const float* cr = cbm + (size_t)c * E_DIM;
            float s = 0.0f;
            #pragma unroll
            for (int g4 = 0; g4 < 4; g4++) {
                float4 c0 = *(const float4*)(cr + g4 * 16);
                float4 c1 = *(const float4*)(cr + g4 * 16 + 4);
                float4 c2 = *(const float4*)(cr + g4 * 16 + 8);
                float4 c3 = *(const float4*)(cr + g4 * 16 + 12);
                const float* zp = zr + g4 * 16;
                s = __fmaf_rn(zp[0],  c0.x, s); s = __fmaf_rn(zp[1],  c0.y, s);
                s = __fmaf_rn(zp[2],  c0.z, s); s = __fmaf_rn(zp[3],  c0.w, s);
                s = __fmaf_rn(zp[4],  c1.x, s); s = __fmaf_rn(zp[5],  c1.y, s);
                s = __fmaf_rn(zp[6],  c1.z, s); s = __fmaf_rn(zp[7],  c1.w, s);
                s = __fmaf_rn(zp[8],  c2.x, s); s = __fmaf_rn(zp[9],  c2.y, s);
                s = __fmaf_rn(zp[10], c2.z, s); s = __fmaf_rn(zp[11], c2.w, s);
                s = __fmaf_rn(zp[12], c3.x, s); s = __fmaf_rn(zp[13], c3.y, s);
                s = __fmaf_rn(zp[14], c3.z, s); s = __fmaf_rn(zp[15], c3.w, s);
            }
            return __fsub_rn(__fadd_rn(zsqv, sesq[c]), __fmul_rn(2.0f, s));
        };

        if (cnt <= CAP) {
            for (int i = start; i < cnt; i += 2) {
                int c = scand[row * CAP + i];
                float d = exact_d(c);
                if (d < bd || (d == bd && c < bi)) { bd = d; bi = c; }
            }
        } else {  // overflow fallback: full exact scan (provably correct, ~never)
            for (int c = start; c < N_E; c += 2) {
                float d = exact_d(c);
                if (d < bd || (d == bd && c < bi)) { bd = d; bi = c; }
            }
        }
        rbd[tid] = bd; rbi[tid] = bi;
    }
    __syncthreads();
    if (tid < 128) {
        float bd = rbd[tid]; int bi = rbi[tid];
        float d2 = rbd[tid + 128]; int i2 = rbi[tid + 128];
        if (d2 < bd || (d2 == bd && i2 < bi)) { bd = d2; bi = i2; }
        swin[tid] = bi;
        outIdx[m * NPOS + n0 + tid] = (float)bi;
        atomicAdd(outBins + bi, 1.0f);   // integer-valued float adds: exact
    }
    __syncthreads();

    // ---- gather winning code rows into sq[row][d], stride 65 (overlay) ----
    float* sq = sm + S_SQ;
    const float* cbm = cbk + (size_t)m * N_E * E_DIM;
    #pragma unroll
    for (int it = 0; it < 8; it++) {
        int i = tid + it * 256;
        int row = i >> 4, d4 = (i & 15) * 4;
        int idx = swin[row];
        float4 v = *(const float4*)(cbm + (size_t)idx * E_DIM + d4);
        float* dp = sq + row * 65 + d4;
        dp[0] = v.x; dp[1] = v.y; dp[2] = v.z; dp[3] = v.w;
    }
    __syncthreads();

    // ---- z_vq = zf + (zq - zf); loss partial in double ----
    double lsum = 0.0;
    float* ob = outZvq + ((size_t)(b * CC_ + m * E_DIM)) * HW_ + p0;
    #pragma unroll
    for (int it = 0; it < 8; it++) {
        int i = tid + it * 256;
        int d = i >> 5, j4 = (i & 31) * 4;
        float o[4];
        #pragma unroll
        for (int q = 0; q < 4; q++) {
            float zf = szt[(j4 + q) * 73 + d];
            float zq = sq[(j4 + q) * 65 + d];
            float df = __fsub_rn(zq, zf);
            o[q] = __fadd_rn(zf, df);
            lsum += (double)df * (double)df;
        }
        *(float4*)(ob + (size_t)d * HW_ + j4) = make_float4(o[0], o[1], o[2], o[3]);
    }

    #pragma unroll
    for (int off = 16; off > 0; off >>= 1)
        lsum += __shfl_down_sync(0xffffffffu, lsum, off);
    if (lane == 0) swarp[wid] = lsum;
    __syncthreads();
    if (wid == 0) {
        double v = (lane < 8) ? swarp[lane] : 0.0;
        #pragma unroll
        for (int off = 4; off > 0; off >>= 1)
            v += __shfl_down_sync(0xffffffffu, v, off);
        if (lane == 0) g_part[m * 128 + blockIdx.x] = v;
    }
}

// ---------------- K3: finalize loss ---------------------------------------------
__global__ void pq_loss_kernel(float* __restrict__ outLoss) {
    __shared__ double sred[256];
    int t = threadIdx.x;
    double s = 0.0;
    for (int i = t; i < 1024; i += 256) s += g_part[i];
    sred[t] = s;
    __syncthreads();
    for (int off = 128; off > 0; off >>= 1) {
        if (t < off) sred[t] += sred[t + off];
        __syncthreads();
    }
    if (t == 0) {
        double loss = 1.25 * sred[0] / (double)((size_t)NPOS * E_DIM);
        outLoss[0] = (float)loss;
    }
}

// ---------------- launch ----------------------------------------------------------
extern "C" void kernel_launch(void* const* d_in, const int* in_sizes, int n_in,
                              void* d_out, int out_size)
{
    const float* z   = (const float*)d_in[0];
    const float* cbk = (const float*)d_in[1];
    if (n_in >= 2 && in_sizes[0] == M_SUB * N_E * E_DIM) {  // swapped-order safety
        z   = (const float*)d_in[1];
        cbk = (const float*)d_in[0];
    }
    float* out = (float*)d_out;
    float* outZvq  = out + OFF_ZVQ;
    float* outLoss = out + OFF_LOSS;
    float* outIdx  = out + OFF_IDX;
    float* outBins = out + OFF_BIN;

    const int dyn_smem = S_TOT * 4;   // 95232 B
    cudaFuncSetAttribute(pq_dist_kernel,
                         cudaFuncAttributeMaxDynamicSharedMemorySize, dyn_smem);

    pq_init_kernel<<<1, 1024>>>(outBins);
    pq_esq_kernel<<<(M_SUB * N_E + 255) / 256, 256>>>(cbk);
    pq_tr_kernel<<<64, 256>>>(cbk);
    dim3 g1(NPOS / 128, M_SUB);
    pq_dist_kernel<<<g1, 256, dyn_smem>>>(z, cbk, outZvq, outIdx, outBins);
    pq_loss_kernel<<<1, 256>>>(outLoss);
}